// round 1
// baseline (speedup 1.0000x reference)
#include <cuda_runtime.h>
#include <math.h>

#define Nn 4096
#define Kn 16
#define K1 17
#define Tt 16
#define NTt 16
#define Dd 128
#define TTe 256
#define NOUTER 3
#define NINNER 5

// ---- precomputed constants (device globals, no allocation) ----
__device__ float g_q[TTe];     // softmax(q0) rows
__device__ float g_cq2[TTe];   // sum_m q[t,m]*C2[t,l,m]^2
__device__ float g_tfn2[TTe];  // ||tf[t,m]||^2
__device__ float g_alpha[2];   // alpha, 1-alpha

__global__ void setup_kernel(const float* __restrict__ q0,
                             const float* __restrict__ tmpl,
                             const float* __restrict__ tf,
                             const float* __restrict__ alpha0) {
    int tid = threadIdx.x;
    __shared__ float qs[TTe];
    if (tid == 0) {
        float a = 1.0f / (1.0f + expf(-alpha0[0]));
        g_alpha[0] = a; g_alpha[1] = 1.0f - a;
    }
    if (tid < Tt) {
        float mx = -3.402823466e38f;
        for (int m = 0; m < NTt; m++) mx = fmaxf(mx, q0[tid*NTt+m]);
        float e[NTt]; float s = 0.0f;
        for (int m = 0; m < NTt; m++) { e[m] = expf(q0[tid*NTt+m] - mx); s += e[m]; }
        float inv = 1.0f / s;
        for (int m = 0; m < NTt; m++) { float v = e[m]*inv; qs[tid*NTt+m] = v; g_q[tid*NTt+m] = v; }
    }
    __syncthreads();
    if (tid < TTe) {
        int t = tid >> 4, l = tid & 15;
        float s = 0.0f;
        for (int m = 0; m < NTt; m++) {
            float c = tmpl[(t*NTt + l)*NTt + m];
            s += qs[t*NTt + m] * c * c;
        }
        g_cq2[tid] = s;
        float s2 = 0.0f;
        const float* p = tf + tid*Dd;
        for (int d = 0; d < Dd; d++) { float v = p[d]; s2 += v*v; }
        g_tfn2[tid] = s2;
    }
}

// shared-memory layout (float offsets)
#define FI_O   0        // 17*128 = 2176  (float4 aligned)
#define C1_O   2176     // 17*20  = 340   (rows padded to 20 for float4)
#define CR_O   2516     // 17
#define FN2_O  2533     // 17
#define NB_O   2550     // 17 ints
#define U_O    2567     // 16*17 = 272
#define V_O    2839     // 16*16 = 256
#define M_O    3096     // 16*272 = 4352 (16B aligned)
#define G_O    7448     // 16*272 = 4352
#define H_O    11800    // 16*320 = 5120 ([l][j] rows padded to 20)
#define SM_FLOATS 16920
#define SM_BYTES (SM_FLOATS*4)

__global__ __launch_bounds__(512, 2)
void ltfgw_kernel(const float* __restrict__ x,
                  const float* __restrict__ adj,
                  const int*   __restrict__ nbr,
                  const float* __restrict__ tmpl,
                  const float* __restrict__ tf,
                  float* __restrict__ out) {
    extern __shared__ float smf[];
    float* Fi   = smf + FI_O;
    float* C1s  = smf + C1_O;
    float* cr   = smf + CR_O;
    float* fn2  = smf + FN2_O;
    int*   nb   = (int*)(smf + NB_O);
    float* ush  = smf + U_O;
    float* vsh  = smf + V_O;
    float* Msh  = smf + M_O;
    float* Gsh  = smf + G_O;
    float* Hsh  = smf + H_O;

    const int n    = blockIdx.x;
    const int tid  = threadIdx.x;
    const int lane = tid & 31;
    const int t    = tid >> 5;   // warp id == template id

    // ---- Phase A: gather neighbor set, features, adjacency submatrix ----
    if (tid < K1) nb[tid] = (tid == 0) ? n : nbr[n*Kn + tid - 1];
    __syncthreads();
    for (int i = tid; i < K1*Dd; i += 512)
        Fi[i] = x[nb[i >> 7]*Dd + (i & 127)];
    for (int i = tid; i < K1*K1; i += 512) {
        int r = i / K1, c = i - r*K1;
        C1s[r*20 + c] = adj[nb[r]*Nn + nb[c]];
    }
    __syncthreads();
    if (tid < K1) {
        float s = 0.0f;
        const float* fr = Fi + tid*Dd;
        for (int d = 0; d < Dd; d++) s = fmaf(fr[d], fr[d], s);
        fn2[tid] = s;
        float s2 = 0.0f;
        const float* c1r = C1s + tid*20;
        for (int j = 0; j < K1; j++) s2 = fmaf(c1r[j], c1r[j], s2);
        cr[tid] = s2 * (1.0f/17.0f);
    }

    // ---- Phase B: M[t][k*16+m] = ||Fi_k||^2 + ||tf_tm||^2 - 2 Fi_k . tf_tm ----
    {
        int tm = tid >> 1, h = tid & 1;      // thread pair splits D in halves
        int tt = tm >> 4, m = tm & 15;
        float acc[K1];
        #pragma unroll
        for (int k = 0; k < K1; k++) acc[k] = 0.0f;
        const float4* tf4 = ((const float4*)tf) + tm*32 + h*16;
        const float4* Fi4 = (const float4*)Fi;
        #pragma unroll
        for (int d4 = 0; d4 < 16; d4++) {
            float4 tv = __ldg(tf4 + d4);
            #pragma unroll
            for (int k = 0; k < K1; k++) {
                float4 fv = Fi4[k*32 + h*16 + d4];
                acc[k] = fmaf(fv.x, tv.x, fmaf(fv.y, tv.y, fmaf(fv.z, tv.z, fmaf(fv.w, tv.w, acc[k]))));
            }
        }
        float* Mt = Msh + tt*272 + m;
        if (h == 0) {
            #pragma unroll
            for (int k = 0; k < K1; k++) Mt[k*16] = acc[k];
        }
        __syncthreads();
        if (h == 1) {
            float tn2 = __ldg(&g_tfn2[tm]);
            #pragma unroll
            for (int k = 0; k < K1; k++)
                Mt[k*16] = fn2[k] + tn2 - 2.0f*(Mt[k*16] + acc[k]);
        }
    }
    // init G0 = p (x) q
    for (int i = tid; i < Tt*272; i += 512) {
        int tt = i / 272; int e = i - tt*272;
        Gsh[i] = (1.0f/17.0f) * g_q[tt*16 + (e & 15)];
    }
    __syncthreads();

    // ---- Phase C: per-warp (per-template) optimal transport ----
    float* Mw = Msh + t*272;
    float* Gw = Gsh + t*272;   // rotates: G -> grad -> K -> G
    float* Hw = Hsh + t*320;   // [l][j], row stride 20
    float* uw = ush + t*17;
    float* vw = vsh + t*16;

    const int l = lane & 15;
    float c2r[16];
    {
        const float* c2 = tmpl + (t*16 + l)*16;
        #pragma unroll
        for (int m = 0; m < 16; m++) c2r[m] = __ldg(c2 + m);
    }
    const float qm    = (lane < 16) ? __ldg(&g_q[t*16 + lane]) : 0.0f;
    const float cq2l  = __ldg(&g_cq2[t*16 + l]);
    const float alpha = g_alpha[0];
    const float oneMa = g_alpha[1];
    const float pinv  = 1.0f/17.0f;

    float outacc = 0.0f;

    for (int outer = 0; outer <= NOUTER; outer++) {
        // H[l][j] = sum_m G[j][m] * C2[t][l][m]
        #pragma unroll
        for (int ii = 0; ii < 9; ii++) {
            int e = lane + 32*ii;
            if (e < 272) {
                int j = e >> 4;
                const float4* Gr = (const float4*)(Gw + j*16);
                float4 a = Gr[0], b = Gr[1], c = Gr[2], d = Gr[3];
                float s =            a.x*c2r[0];
                s = fmaf(a.y, c2r[1],  s); s = fmaf(a.z, c2r[2],  s); s = fmaf(a.w, c2r[3],  s);
                s = fmaf(b.x, c2r[4],  s); s = fmaf(b.y, c2r[5],  s); s = fmaf(b.z, c2r[6],  s); s = fmaf(b.w, c2r[7],  s);
                s = fmaf(c.x, c2r[8],  s); s = fmaf(c.y, c2r[9],  s); s = fmaf(c.z, c2r[10], s); s = fmaf(c.w, c2r[11], s);
                s = fmaf(d.x, c2r[12], s); s = fmaf(d.y, c2r[13], s); s = fmaf(d.z, c2r[14], s); s = fmaf(d.w, c2r[15], s);
                Hw[l*20 + j] = s;
            }
        }
        __syncwarp();

        // grad[k][l] = (1-a)M + a*(cr[k] + cq2[l] - 2*sum_j C1[k][j] H[l][j])
        float mn =  3.402823466e38f, mx = -3.402823466e38f;
        const float4* h4 = (const float4*)(Hw + l*20);
        float4 hb0 = h4[0], hb1 = h4[1], hb2 = h4[2], hb3 = h4[3];
        float  hb4 = Hw[l*20 + 16];
        #pragma unroll
        for (int ii = 0; ii < 9; ii++) {
            int e = lane + 32*ii;
            if (e < 272) {
                int k = e >> 4;
                const float4* c14 = (const float4*)(C1s + k*20);
                float4 a = c14[0], b = c14[1], c = c14[2], d = c14[3];
                float s =            a.x*hb0.x;
                s = fmaf(a.y, hb0.y, s); s = fmaf(a.z, hb0.z, s); s = fmaf(a.w, hb0.w, s);
                s = fmaf(b.x, hb1.x, s); s = fmaf(b.y, hb1.y, s); s = fmaf(b.z, hb1.z, s); s = fmaf(b.w, hb1.w, s);
                s = fmaf(c.x, hb2.x, s); s = fmaf(c.y, hb2.y, s); s = fmaf(c.z, hb2.z, s); s = fmaf(c.w, hb2.w, s);
                s = fmaf(d.x, hb3.x, s); s = fmaf(d.y, hb3.y, s); s = fmaf(d.z, hb3.z, s); s = fmaf(d.w, hb3.w, s);
                s = fmaf(C1s[k*20 + 16], hb4, s);
                float g = oneMa*Mw[e] + alpha*(cr[k] + cq2l - 2.0f*s);
                if (outer < NOUTER) {
                    Gw[e] = g;                       // grad overwrites G (dead now)
                    mn = fminf(mn, g); mx = fmaxf(mx, g);
                } else {
                    outacc += g * Gw[e];             // final objective contribution
                }
            }
        }
        if (outer == NOUTER) break;
        __syncwarp();

        #pragma unroll
        for (int s = 16; s > 0; s >>= 1) {
            mn = fminf(mn, __shfl_xor_sync(0xffffffffu, mn, s));
            mx = fmaxf(mx, __shfl_xor_sync(0xffffffffu, mx, s));
        }
        float inv_eps = __fdividef(1.0f, 0.1f*(mx - mn) + 1e-16f);

        // K = exp(-(grad - lo)/eps), in place
        #pragma unroll
        for (int ii = 0; ii < 9; ii++) {
            int e = lane + 32*ii;
            if (e < 272) Gw[e] = __expf((mn - Gw[e]) * inv_eps);
        }
        __syncwarp();

        // Sinkhorn: u = p/max(Kv), v = q/max(K^T u), 5 iters, v0 = 1
        if (lane < 16) vw[lane] = 1.0f;
        __syncwarp();
        for (int it = 0; it < NINNER; it++) {
            if (lane < K1) {
                float s = 0.0f;
                const float* Kr = Gw + lane*16;
                #pragma unroll
                for (int m = 0; m < 16; m++) s = fmaf(Kr[m], vw[m], s);
                uw[lane] = __fdividef(pinv, fmaxf(s, 1e-16f));
            }
            __syncwarp();
            if (lane < 16) {
                float s = 0.0f;
                #pragma unroll
                for (int k = 0; k < K1; k++) s = fmaf(Gw[k*16 + lane], uw[k], s);
                vw[lane] = __fdividef(qm, fmaxf(s, 1e-16f));
            }
            __syncwarp();
        }
        // G = u * K * v in place
        #pragma unroll
        for (int ii = 0; ii < 9; ii++) {
            int e = lane + 32*ii;
            if (e < 272) Gw[e] *= uw[e >> 4] * vw[e & 15];
        }
        __syncwarp();
    }

    #pragma unroll
    for (int s = 16; s > 0; s >>= 1)
        outacc += __shfl_xor_sync(0xffffffffu, outacc, s);
    if (lane == 0) out[n*Tt + t] = outacc;
}

extern "C" void kernel_launch(void* const* d_in, const int* in_sizes, int n_in,
                              void* d_out, int out_size) {
    const float* x    = (const float*)d_in[0];
    const float* adj  = (const float*)d_in[1];
    const int*   nbr  = (const int*)  d_in[2];
    const float* tmpl = (const float*)d_in[3];
    const float* tf   = (const float*)d_in[4];
    const float* q0   = (const float*)d_in[5];
    const float* a0   = (const float*)d_in[6];
    float* out = (float*)d_out;

    static bool attr_set = false;
    // idempotent attribute set (not a stream op; safe under graph capture)
    cudaFuncSetAttribute(ltfgw_kernel, cudaFuncAttributeMaxDynamicSharedMemorySize, SM_BYTES);

    setup_kernel<<<1, 256>>>(q0, tmpl, tf, a0);
    ltfgw_kernel<<<Nn, 512, SM_BYTES>>>(x, adj, nbr, tmpl, tf, out);
    (void)attr_set; (void)in_sizes; (void)n_in; (void)out_size;
}

// round 3
// speedup vs baseline: 1.6370x; 1.6370x over previous
#include <cuda_runtime.h>
#include <math.h>

#define Nn 4096
#define Kn 16
#define K1 17
#define Tt 16
#define NTt 16
#define Dd 128
#define TTe 256
#define NOUTER 3
#define NINNER 5

// ---- precomputed constants (device globals, no allocation) ----
__device__ float g_q[TTe];     // softmax(q0) rows
__device__ float g_cq2[TTe];   // sum_m q[t,m]*C2[t,l,m]^2
__device__ float g_tfn2[TTe];  // ||tf[t,m]||^2
__device__ float g_alpha[2];   // alpha, 1-alpha

__global__ void setup_kernel(const float* __restrict__ q0,
                             const float* __restrict__ tmpl,
                             const float* __restrict__ tf,
                             const float* __restrict__ alpha0) {
    int tid = threadIdx.x;
    __shared__ float qs[TTe];
    if (tid == 0) {
        float a = 1.0f / (1.0f + expf(-alpha0[0]));
        g_alpha[0] = a; g_alpha[1] = 1.0f - a;
    }
    if (tid < Tt) {
        float mx = -3.402823466e38f;
        for (int m = 0; m < NTt; m++) mx = fmaxf(mx, q0[tid*NTt+m]);
        float e[NTt]; float s = 0.0f;
        for (int m = 0; m < NTt; m++) { e[m] = expf(q0[tid*NTt+m] - mx); s += e[m]; }
        float inv = 1.0f / s;
        for (int m = 0; m < NTt; m++) { float v = e[m]*inv; qs[tid*NTt+m] = v; g_q[tid*NTt+m] = v; }
    }
    __syncthreads();
    if (tid < TTe) {
        int t = tid >> 4, l = tid & 15;
        float s = 0.0f;
        for (int m = 0; m < NTt; m++) {
            float c = tmpl[(t*NTt + l)*NTt + m];
            s += qs[t*NTt + m] * c * c;
        }
        g_cq2[tid] = s;
        float s2 = 0.0f;
        const float* p = tf + tid*Dd;
        for (int d = 0; d < Dd; d++) { float v = p[d]; s2 += v*v; }
        g_tfn2[tid] = s2;
    }
}

// shared-memory layout (float offsets)
#define FI_O   0        // 17*128 = 2176  (float4 aligned)
#define C1_O   2176     // 17*20  = 340   (rows padded to 20 for float4)
#define CR_O   2516     // 17
#define FN2_O  2533     // 17
#define NB_O   2550     // 17 ints
#define U_O    2567     // 16*17 = 272
#define V_O    2839     // 16*16 = 256
#define M_O    3096     // 16*272 = 4352 (16B aligned)
#define G_O    7448     // 16*272 = 4352
#define H_O    11800    // 16*320 = 5120 ([l][j] rows padded to 20)
#define SM_FLOATS 16920
#define SM_BYTES (SM_FLOATS*4)

__global__ __launch_bounds__(512, 2)
void ltfgw_kernel(const float* __restrict__ x,
                  const float* __restrict__ adj,
                  const int*   __restrict__ nbr,
                  const float* __restrict__ tmpl,
                  const float* __restrict__ tf,
                  float* __restrict__ out) {
    extern __shared__ float smf[];
    float* Fi   = smf + FI_O;
    float* C1s  = smf + C1_O;
    float* cr   = smf + CR_O;
    float* fn2  = smf + FN2_O;
    int*   nb   = (int*)(smf + NB_O);
    float* ush  = smf + U_O;
    float* vsh  = smf + V_O;
    float* Msh  = smf + M_O;
    float* Gsh  = smf + G_O;
    float* Hsh  = smf + H_O;

    const int n    = blockIdx.x;
    const int tid  = threadIdx.x;
    const int lane = tid & 31;
    const int t    = tid >> 5;   // warp id == template id

    // ---- Phase A: gather neighbor set, features, adjacency submatrix ----
    if (tid < K1) nb[tid] = (tid == 0) ? n : nbr[n*Kn + tid - 1];
    __syncthreads();
    for (int i = tid; i < K1*Dd; i += 512)
        Fi[i] = x[nb[i >> 7]*Dd + (i & 127)];
    for (int i = tid; i < K1*K1; i += 512) {
        int r = i / K1, c = i - r*K1;
        C1s[r*20 + c] = adj[nb[r]*Nn + nb[c]];
    }
    __syncthreads();
    if (tid < K1) {
        float s = 0.0f;
        const float* fr = Fi + tid*Dd;
        for (int d = 0; d < Dd; d++) s = fmaf(fr[d], fr[d], s);
        fn2[tid] = s;
        float s2 = 0.0f;
        const float* c1r = C1s + tid*20;
        for (int j = 0; j < K1; j++) s2 = fmaf(c1r[j], c1r[j], s2);
        cr[tid] = s2 * (1.0f/17.0f);
    }

    // ---- Phase B: M[t][k*16+m] = ||Fi_k||^2 + ||tf_tm||^2 - 2 Fi_k . tf_tm ----
    {
        int tm = tid >> 1, h = tid & 1;      // thread pair splits D in halves
        int tt = tm >> 4, m = tm & 15;
        float acc[K1];
        #pragma unroll
        for (int k = 0; k < K1; k++) acc[k] = 0.0f;
        const float4* tf4 = ((const float4*)tf) + tm*32 + h*16;
        const float4* Fi4 = (const float4*)Fi;
        #pragma unroll
        for (int d4 = 0; d4 < 16; d4++) {
            float4 tv = __ldg(tf4 + d4);
            #pragma unroll
            for (int k = 0; k < K1; k++) {
                float4 fv = Fi4[k*32 + h*16 + d4];
                acc[k] = fmaf(fv.x, tv.x, fmaf(fv.y, tv.y, fmaf(fv.z, tv.z, fmaf(fv.w, tv.w, acc[k]))));
            }
        }
        float* Mt = Msh + tt*272 + m;
        if (h == 0) {
            #pragma unroll
            for (int k = 0; k < K1; k++) Mt[k*16] = acc[k];
        }
        __syncthreads();
        if (h == 1) {
            float tn2 = __ldg(&g_tfn2[tm]);
            #pragma unroll
            for (int k = 0; k < K1; k++)
                Mt[k*16] = fn2[k] + tn2 - 2.0f*(Mt[k*16] + acc[k]);
        }
    }
    // init G0 = p (x) q
    for (int i = tid; i < Tt*272; i += 512) {
        int tt = i / 272; int e = i - tt*272;
        Gsh[i] = (1.0f/17.0f) * g_q[tt*16 + (e & 15)];
    }
    __syncthreads();

    // ---- Phase C: per-warp (per-template) optimal transport ----
    float* Mw = Msh + t*272;
    float* Gw = Gsh + t*272;   // rotates: G -> grad -> K -> G
    float* Hw = Hsh + t*320;   // [l][j], row stride 20
    float* uw = ush + t*17;
    float* vw = vsh + t*16;

    const int l = lane & 15;
    float c2r[16];
    {
        const float* c2 = tmpl + (t*16 + l)*16;
        #pragma unroll
        for (int m = 0; m < 16; m++) c2r[m] = __ldg(c2 + m);
    }
    const float qm    = (lane < 16) ? __ldg(&g_q[t*16 + lane]) : 0.0f;
    const float cq2l  = __ldg(&g_cq2[t*16 + l]);
    const float alpha = g_alpha[0];
    const float oneMa = g_alpha[1];
    const float pinv  = 1.0f/17.0f;

    float outacc = 0.0f;

    for (int outer = 0; outer <= NOUTER; outer++) {
        // H[l][j] = sum_m G[j][m] * C2[t][l][m]
        #pragma unroll
        for (int ii = 0; ii < 9; ii++) {
            int e = lane + 32*ii;
            if (e < 272) {
                int j = e >> 4;
                const float4* Gr = (const float4*)(Gw + j*16);
                float4 a = Gr[0], b = Gr[1], c = Gr[2], d = Gr[3];
                float s =            a.x*c2r[0];
                s = fmaf(a.y, c2r[1],  s); s = fmaf(a.z, c2r[2],  s); s = fmaf(a.w, c2r[3],  s);
                s = fmaf(b.x, c2r[4],  s); s = fmaf(b.y, c2r[5],  s); s = fmaf(b.z, c2r[6],  s); s = fmaf(b.w, c2r[7],  s);
                s = fmaf(c.x, c2r[8],  s); s = fmaf(c.y, c2r[9],  s); s = fmaf(c.z, c2r[10], s); s = fmaf(c.w, c2r[11], s);
                s = fmaf(d.x, c2r[12], s); s = fmaf(d.y, c2r[13], s); s = fmaf(d.z, c2r[14], s); s = fmaf(d.w, c2r[15], s);
                Hw[l*20 + j] = s;
            }
        }
        __syncwarp();

        // grad[k][l] = (1-a)M + a*(cr[k] + cq2[l] - 2*sum_j C1[k][j] H[l][j])
        float mn =  3.402823466e38f, mx = -3.402823466e38f;
        const float4* h4 = (const float4*)(Hw + l*20);
        float4 hb0 = h4[0], hb1 = h4[1], hb2 = h4[2], hb3 = h4[3];
        float  hb4 = Hw[l*20 + 16];
        #pragma unroll
        for (int ii = 0; ii < 9; ii++) {
            int e = lane + 32*ii;
            if (e < 272) {
                int k = e >> 4;
                const float4* c14 = (const float4*)(C1s + k*20);
                float4 a = c14[0], b = c14[1], c = c14[2], d = c14[3];
                float s =            a.x*hb0.x;
                s = fmaf(a.y, hb0.y, s); s = fmaf(a.z, hb0.z, s); s = fmaf(a.w, hb0.w, s);
                s = fmaf(b.x, hb1.x, s); s = fmaf(b.y, hb1.y, s); s = fmaf(b.z, hb1.z, s); s = fmaf(b.w, hb1.w, s);
                s = fmaf(c.x, hb2.x, s); s = fmaf(c.y, hb2.y, s); s = fmaf(c.z, hb2.z, s); s = fmaf(c.w, hb2.w, s);
                s = fmaf(d.x, hb3.x, s); s = fmaf(d.y, hb3.y, s); s = fmaf(d.z, hb3.z, s); s = fmaf(d.w, hb3.w, s);
                s = fmaf(C1s[k*20 + 16], hb4, s);
                float g = oneMa*Mw[e] + alpha*(cr[k] + cq2l - 2.0f*s);
                if (outer < NOUTER) {
                    Gw[e] = g;                       // grad overwrites G (dead now)
                    mn = fminf(mn, g); mx = fmaxf(mx, g);
                } else {
                    outacc += g * Gw[e];             // final objective contribution
                }
            }
        }
        if (outer == NOUTER) break;
        __syncwarp();

        #pragma unroll
        for (int s = 16; s > 0; s >>= 1) {
            mn = fminf(mn, __shfl_xor_sync(0xffffffffu, mn, s));
            mx = fmaxf(mx, __shfl_xor_sync(0xffffffffu, mx, s));
        }
        float inv_eps = __fdividef(1.0f, 0.1f*(mx - mn) + 1e-16f);

        // K = exp(-(grad - lo)/eps), in place
        #pragma unroll
        for (int ii = 0; ii < 9; ii++) {
            int e = lane + 32*ii;
            if (e < 272) Gw[e] = __expf((mn - Gw[e]) * inv_eps);
        }
        __syncwarp();

        // Sinkhorn: u = p/max(Kv), v = q/max(K^T u), 5 iters, v0 = 1
        if (lane < 16) vw[lane] = 1.0f;
        __syncwarp();
        for (int it = 0; it < NINNER; it++) {
            if (lane < K1) {
                float s = 0.0f;
                const float* Kr = Gw + lane*16;
                #pragma unroll
                for (int m = 0; m < 16; m++) s = fmaf(Kr[m], vw[m], s);
                uw[lane] = __fdividef(pinv, fmaxf(s, 1e-16f));
            }
            __syncwarp();
            if (lane < 16) {
                float s = 0.0f;
                #pragma unroll
                for (int k = 0; k < K1; k++) s = fmaf(Gw[k*16 + lane], uw[k], s);
                vw[lane] = __fdividef(qm, fmaxf(s, 1e-16f));
            }
            __syncwarp();
        }
        // G = u * K * v in place
        #pragma unroll
        for (int ii = 0; ii < 9; ii++) {
            int e = lane + 32*ii;
            if (e < 272) Gw[e] *= uw[e >> 4] * vw[e & 15];
        }
        __syncwarp();
    }

    #pragma unroll
    for (int s = 16; s > 0; s >>= 1)
        outacc += __shfl_xor_sync(0xffffffffu, outacc, s);
    if (lane == 0) out[n*Tt + t] = outacc;
}

extern "C" void kernel_launch(void* const* d_in, const int* in_sizes, int n_in,
                              void* d_out, int out_size) {
    const float* x    = (const float*)d_in[0];
    const float* adj  = (const float*)d_in[1];
    const int*   nbr  = (const int*)  d_in[2];
    const float* tmpl = (const float*)d_in[3];
    const float* tf   = (const float*)d_in[4];
    const float* q0   = (const float*)d_in[5];
    const float* a0   = (const float*)d_in[6];
    float* out = (float*)d_out;

    static bool attr_set = false;
    // idempotent attribute set (not a stream op; safe under graph capture)
    cudaFuncSetAttribute(ltfgw_kernel, cudaFuncAttributeMaxDynamicSharedMemorySize, SM_BYTES);

    setup_kernel<<<1, 256>>>(q0, tmpl, tf, a0);
    ltfgw_kernel<<<Nn, 512, SM_BYTES>>>(x, adj, nbr, tmpl, tf, out);
    (void)attr_set; (void)in_sizes; (void)n_in; (void)out_size;
}

// round 4
// speedup vs baseline: 5.5644x; 3.3991x over previous
#include <cuda_runtime.h>
#include <math.h>

#define Nn 4096
#define Kn 16
#define K1 17
#define Tt 16
#define NTt 16
#define Dd 128
#define TTe 256
#define PINV (1.0f/17.0f)
#define TINYF 1e-16f

// ---- device globals (static, no runtime allocation) ----
__device__ float g_q[TTe];      // softmax(q0)
__device__ float g_cq2[TTe];    // sum_m q[t,m]*C2[t,l,m]^2
__device__ float g_qc2[TTe];    // sum_m q[t,m]*C2[t,l,m]
__device__ float g_tfn2[TTe];   // ||tf[t,m]||^2 (unused by main, kept for setup completeness)
__device__ float g_alpha[2];    // alpha, 1-alpha
__device__ float g_XT[Nn*TTe];  // XT[n][tm] = ||x_n||^2 + ||tf_tm||^2 - 2<x_n,tf_tm>

// ============================ setup ============================
__global__ void setup_kernel(const float* __restrict__ q0,
                             const float* __restrict__ tmpl,
                             const float* __restrict__ tf,
                             const float* __restrict__ alpha0) {
    int tid = threadIdx.x;
    __shared__ float qs[TTe];
    if (tid == 0) {
        float a = 1.0f / (1.0f + expf(-alpha0[0]));
        g_alpha[0] = a; g_alpha[1] = 1.0f - a;
    }
    if (tid < Tt) {
        float mx = -3.402823466e38f;
        for (int m = 0; m < NTt; m++) mx = fmaxf(mx, q0[tid*NTt+m]);
        float e[NTt]; float s = 0.0f;
        for (int m = 0; m < NTt; m++) { e[m] = expf(q0[tid*NTt+m] - mx); s += e[m]; }
        float inv = 1.0f / s;
        for (int m = 0; m < NTt; m++) { float v = e[m]*inv; qs[tid*NTt+m] = v; g_q[tid*NTt+m] = v; }
    }
    __syncthreads();
    if (tid < TTe) {
        int t = tid >> 4;
        float s = 0.0f, s3 = 0.0f;
        for (int m = 0; m < NTt; m++) {
            float c = tmpl[tid*NTt + m];
            float qq = qs[t*NTt + m];
            s  += qq * c * c;
            s3 += qq * c;
        }
        g_cq2[tid] = s;
        g_qc2[tid] = s3;
        float s2 = 0.0f;
        const float* p = tf + tid*Dd;
        for (int d = 0; d < Dd; d++) { float v = p[d]; s2 += v*v; }
        g_tfn2[tid] = s2;
    }
}

// ================= XT = xn2 + tn2 - 2 x@tf^T =================
#define GSM_BYTES (2*64*33*16 + 2*64*4)
__global__ __launch_bounds__(256)
void gemm_xt_kernel(const float* __restrict__ x, const float* __restrict__ tf) {
    extern __shared__ float4 gsm[];
    float4* xs = gsm;              // 64 x 33 float4 (row pad 1)
    float4* ts = gsm + 64*33;
    float*  xn2 = (float*)(gsm + 2*64*33);
    float*  tn2 = xn2 + 64;
    int tid = threadIdx.x;
    int n0 = blockIdx.x*64, m0 = blockIdx.y*64;
    const float4* xg = (const float4*)(x + (size_t)n0*Dd);
    const float4* tg = (const float4*)(tf + (size_t)m0*Dd);
    for (int i = tid; i < 64*32; i += 256) {
        int r = i >> 5, c = i & 31;
        xs[r*33+c] = xg[r*32+c];
        ts[r*33+c] = tg[r*32+c];
    }
    __syncthreads();
    if (tid < 128) {
        int r = tid & 63;
        const float4* src = (tid < 64) ? (xs + r*33) : (ts + r*33);
        float s = 0.0f;
        #pragma unroll 8
        for (int c = 0; c < 32; c++) {
            float4 v = src[c];
            s += v.x*v.x + v.y*v.y + v.z*v.z + v.w*v.w;
        }
        if (tid < 64) xn2[r] = s; else tn2[r] = s;
    }
    __syncthreads();
    int tx = tid & 15, ty = tid >> 4;
    float acc[4][4];
    #pragma unroll
    for (int i = 0; i < 4; i++)
        #pragma unroll
        for (int j = 0; j < 4; j++) acc[i][j] = 0.0f;
    #pragma unroll 4
    for (int k = 0; k < 32; k++) {
        float4 a[4], b[4];
        #pragma unroll
        for (int i = 0; i < 4; i++) a[i] = xs[(ty*4+i)*33 + k];
        #pragma unroll
        for (int j = 0; j < 4; j++) b[j] = ts[(tx*4+j)*33 + k];
        #pragma unroll
        for (int i = 0; i < 4; i++)
            #pragma unroll
            for (int j = 0; j < 4; j++)
                acc[i][j] = fmaf(a[i].x, b[j].x, fmaf(a[i].y, b[j].y,
                             fmaf(a[i].z, b[j].z, fmaf(a[i].w, b[j].w, acc[i][j]))));
    }
    #pragma unroll
    for (int i = 0; i < 4; i++) {
        int n = n0 + ty*4 + i;
        #pragma unroll
        for (int j = 0; j < 4; j++) {
            int m = m0 + tx*4 + j;
            g_XT[(size_t)n*TTe + m] = xn2[ty*4+i] + tn2[tx*4+j] - 2.0f*acc[i][j];
        }
    }
}

// ======================= main kernel =======================
// smem layout (float offsets)
#define NB_O   0     // 17 int
#define RB_O   17    // 17 int (row bitmasks)
#define JL_O   34    // 18 int (compacted nonzero-row list)
#define PC_O   52    // 1 int
#define T1_O   53    // 17 float: alpha*pinv*cnt[k]
#define U_O    72    // 16 warps * 18
#define V_O    360   // 16 * 16
#define M_O    616   // 16 * 272
#define H_O    4968  // 16 * 272   H[j*16+l]
#define KT_O   9320  // 16 * 272   Kt[m*17+k]
#define SM_FLOATS 13672
#define SM_BYTES (SM_FLOATS*4)

__global__ __launch_bounds__(512, 2)
void ltfgw_kernel(const float* __restrict__ adj,
                  const int*   __restrict__ nbr,
                  const float* __restrict__ tmpl,
                  float* __restrict__ out) {
    extern __shared__ float smf[];
    int*   nb      = (int*)(smf + NB_O);
    int*   rowbits = (int*)(smf + RB_O);
    int*   jlist   = (int*)(smf + JL_O);
    int*   PC      = (int*)(smf + PC_O);
    float* t1f     = smf + T1_O;

    const int n    = blockIdx.x;
    const int tid  = threadIdx.x;
    const int lane = tid & 31;
    const int t    = tid >> 5;
    const int l    = lane & 15;
    const int h    = lane >> 4;

    float* uw  = smf + U_O + t*18;
    float* vw  = smf + V_O + t*16;
    float* Mw  = smf + M_O + t*272;
    float* Hw  = smf + H_O + t*272;
    float* Ktw = smf + KT_O + t*272;

    const float alpha = g_alpha[0];
    const float oneMa = g_alpha[1];
    const float twoA  = 2.0f*alpha;

    // ---- Phase A1: neighbor list ----
    if (tid < K1) nb[tid] = (tid == 0) ? n : nbr[n*Kn + tid - 1];
    __syncthreads();

    // ---- Phase A2: M gather (all warps) ----
    #pragma unroll
    for (int ii = 0; ii < 9; ii++) {
        int e = lane + 32*ii;
        if (e < 272) {
            int k = e >> 4;
            Mw[e] = g_XT[nb[k]*TTe + t*16 + (e & 15)];
        }
    }
    // ---- Phase A3 (warp 0): row masks of the binary 17x17 C1 ----
    if (tid < 32) {
        int bits = 0; float cnt = 0.0f;
        if (tid < K1) {
            const float* arow = adj + (size_t)nb[tid]*Nn;
            for (int c = 0; c < K1; c++) {
                float v = arow[nb[c]];
                if (v != 0.0f) { bits |= (1 << c); cnt += 1.0f; }
            }
            rowbits[tid] = bits;
            t1f[tid] = alpha * PINV * cnt;   // = alpha*cr[k]; rs[k]=cnt
        }
        unsigned nz = __ballot_sync(0xffffffffu, bits != 0);
        if (bits) jlist[__popc(nz & ((1u << tid) - 1u))] = tid;
        if (tid == 0) PC[0] = __popc(nz);
    }
    __syncthreads();

    const int P = PC[0];
    const int lastOuter = (P == 0) ? 1 : 3;

    // ---- per-warp constants ----
    float c2r[16];
    {
        const float4* c2 = (const float4*)(tmpl + (t*16 + l)*16);
        #pragma unroll
        for (int i = 0; i < 4; i++) {
            float4 v = __ldg(c2 + i);
            c2r[4*i+0] = v.x; c2r[4*i+1] = v.y; c2r[4*i+2] = v.z; c2r[4*i+3] = v.w;
        }
    }
    const float qreg  = __ldg(&g_q[t*16 + l]);
    const float ac    = alpha * __ldg(&g_cq2[t*16 + l]);
    const float lanec = 1.0f - 2.0f * __ldg(&g_qc2[t*16 + l]);

    float ge[9];
    float karr[9];
    float vreg = 1.0f;

    for (int outer = 0; ; outer++) {
        // ---------- grad ----------
        if (outer == 0) {
            // analytic: H0[l][j] = pinv*qc2[t,l] for every j
            #pragma unroll
            for (int ii = 0; ii < 9; ii++) {
                int e = lane + 32*ii;
                if (e < 272) {
                    int k = e >> 4;
                    ge[ii] = fmaf(oneMa, Mw[e], fmaf(t1f[k], lanec, ac));
                }
            }
        } else {
            #pragma unroll
            for (int ii = 0; ii < 9; ii++) {
                int e = lane + 32*ii;
                if (e < 272) {
                    int k = e >> 4;
                    int bits = rowbits[k];
                    float s = 0.0f;
                    while (bits) {
                        int j = __ffs(bits) - 1;
                        bits &= bits - 1;
                        s += Hw[j*16 + l];
                    }
                    ge[ii] = fmaf(oneMa, Mw[e], fmaf(-twoA, s, ac + t1f[k]));
                }
            }
        }

        if (outer == lastOuter) {
            // final objective: sum grad * G, G = u (x) v * K
            float acc = 0.0f;
            #pragma unroll
            for (int ii = 0; ii < 9; ii++) {
                int e = lane + 32*ii;
                if (e < 272) {
                    int k = e >> 4;
                    acc = fmaf(ge[ii]*karr[ii], uw[k]*vreg, acc);
                }
            }
            #pragma unroll
            for (int s = 16; s > 0; s >>= 1)
                acc += __shfl_xor_sync(0xffffffffu, acc, s);
            if (lane == 0) out[n*Tt + t] = acc;
            break;
        }

        // ---------- eps + K = exp ----------
        float mn = 3.402823466e38f, mx = -3.402823466e38f;
        #pragma unroll
        for (int ii = 0; ii < 8; ii++) { mn = fminf(mn, ge[ii]); mx = fmaxf(mx, ge[ii]); }
        if (lane < 16) { mn = fminf(mn, ge[8]); mx = fmaxf(mx, ge[8]); }
        #pragma unroll
        for (int s = 16; s > 0; s >>= 1) {
            mn = fminf(mn, __shfl_xor_sync(0xffffffffu, mn, s));
            mx = fmaxf(mx, __shfl_xor_sync(0xffffffffu, mx, s));
        }
        float inv_eps = __fdividef(1.0f, 0.1f*(mx - mn) + TINYF);

        #pragma unroll
        for (int ii = 0; ii < 9; ii++) {
            int e = lane + 32*ii;
            if (e < 272) {
                float kv = __expf((mn - ge[ii]) * inv_eps);
                karr[ii] = kv;
                Ktw[(e & 15)*17 + (e >> 4)] = kv;   // transposed, stride 17: conflict-free
            } else karr[ii] = 0.0f;
        }
        __syncwarp();

        // ---------- Sinkhorn (5 iters) ----------
        { // first u-step with v = 1
            float s = 0.0f;
            if (lane < K1) {
                #pragma unroll
                for (int m = 0; m < 16; m++) s += Ktw[m*17 + lane];
            }
            float u = __fdividef(PINV, fmaxf(s, TINYF));
            if (lane < K1) uw[lane] = u;
        }
        __syncwarp();
        #pragma unroll
        for (int it = 0; it < 5; it++) {
            // v-step: per lane m = lane&15, parity h; K in regs
            float sv = 0.0f;
            #pragma unroll
            for (int r = 0; r < 8; r++) sv = fmaf(karr[r], uw[2*r + h], sv);
            if (lane < 16) sv = fmaf(karr[8], uw[16], sv);
            sv += __shfl_xor_sync(0xffffffffu, sv, 16);
            vreg = __fdividef(qreg, fmaxf(sv, TINYF));
            if (it == 4) break;
            // u-step: lane k reads Kt column-major (conflict-free), v via shuffles
            float s = 0.0f;
            #pragma unroll
            for (int m = 0; m < 16; m++) {
                float vm = __shfl_sync(0xffffffffu, vreg, m);
                if (lane < K1) s = fmaf(Ktw[m*17 + lane], vm, s);
            }
            float u = __fdividef(PINV, fmaxf(s, TINYF));
            if (lane < K1) uw[lane] = u;
            __syncwarp();
        }

        // ---------- build H for next grad (masked j only) ----------
        if (P > 0) {
            if (lane < 16) vw[lane] = vreg;
            __syncwarp();
            for (int rd = 0; 2*rd < P; rd++) {
                int idx = 2*rd + h;
                bool val = idx < P;
                int j = jlist[val ? idx : 0];
                float uj = uw[j];
                float s = 0.0f;
                #pragma unroll
                for (int m = 0; m < 16; m++)
                    s = fmaf(Ktw[m*17 + j] * vw[m], c2r[m], s);
                if (val) Hw[j*16 + l] = uj * s;
            }
            __syncwarp();
        }
    }
}

extern "C" void kernel_launch(void* const* d_in, const int* in_sizes, int n_in,
                              void* d_out, int out_size) {
    const float* x    = (const float*)d_in[0];
    const float* adj  = (const float*)d_in[1];
    const int*   nbr  = (const int*)  d_in[2];
    const float* tmpl = (const float*)d_in[3];
    const float* tf   = (const float*)d_in[4];
    const float* q0   = (const float*)d_in[5];
    const float* a0   = (const float*)d_in[6];
    float* out = (float*)d_out;

    cudaFuncSetAttribute(gemm_xt_kernel, cudaFuncAttributeMaxDynamicSharedMemorySize, GSM_BYTES);
    cudaFuncSetAttribute(ltfgw_kernel,   cudaFuncAttributeMaxDynamicSharedMemorySize, SM_BYTES);

    setup_kernel<<<1, 256>>>(q0, tmpl, tf, a0);
    dim3 ggrid(Nn/64, TTe/64);
    gemm_xt_kernel<<<ggrid, 256, GSM_BYTES>>>(x, tf);
    ltfgw_kernel<<<Nn, 512, SM_BYTES>>>(adj, nbr, tmpl, out);
    (void)in_sizes; (void)n_in; (void)out_size;
}

// round 6
// speedup vs baseline: 6.7484x; 1.2128x over previous
#include <cuda_runtime.h>
#include <math.h>

#define Nn 4096
#define Kn 16
#define K1 17
#define Tt 16
#define NTt 16
#define Dd 128
#define TTe 256
#define PINV (1.0f/17.0f)
#define TINYF 1e-16f

// ---- device globals (static, no runtime allocation) ----
__device__ float g_q[TTe];      // softmax(q0)
__device__ float g_cq2[TTe];    // sum_m q[t,m]*C2[t,l,m]^2
__device__ float g_qc2[TTe];    // sum_m q[t,m]*C2[t,l,m]
__device__ float g_alpha[2];    // alpha, 1-alpha
__device__ float g_XT[Nn*TTe];  // XT[n][tm] = ||x_n||^2 + ||tf_tm||^2 - 2<x_n,tf_tm>

// ============================ setup ============================
__global__ void setup_kernel(const float* __restrict__ q0,
                             const float* __restrict__ tmpl,
                             const float* __restrict__ alpha0) {
    int tid = threadIdx.x;
    __shared__ float qs[TTe];
    if (tid == 0) {
        float a = 1.0f / (1.0f + expf(-alpha0[0]));
        g_alpha[0] = a; g_alpha[1] = 1.0f - a;
    }
    if (tid < Tt) {
        float mx = -3.402823466e38f;
        for (int m = 0; m < NTt; m++) mx = fmaxf(mx, q0[tid*NTt+m]);
        float e[NTt]; float s = 0.0f;
        for (int m = 0; m < NTt; m++) { e[m] = expf(q0[tid*NTt+m] - mx); s += e[m]; }
        float inv = 1.0f / s;
        for (int m = 0; m < NTt; m++) { float v = e[m]*inv; qs[tid*NTt+m] = v; g_q[tid*NTt+m] = v; }
    }
    __syncthreads();
    if (tid < TTe) {
        int t = tid >> 4;
        float s = 0.0f, s3 = 0.0f;
        const float4* c4 = (const float4*)(tmpl + tid*NTt);
        #pragma unroll
        for (int i = 0; i < 4; i++) {
            float4 c = c4[i];
            const float* qq = qs + t*NTt + 4*i;
            s  += qq[0]*c.x*c.x + qq[1]*c.y*c.y + qq[2]*c.z*c.z + qq[3]*c.w*c.w;
            s3 += qq[0]*c.x     + qq[1]*c.y     + qq[2]*c.z     + qq[3]*c.w;
        }
        g_cq2[tid] = s;
        g_qc2[tid] = s3;
    }
}

// ================= XT = xn2 + tn2 - 2 x@tf^T =================
#define GSM_BYTES (2*64*33*16 + 2*64*4)
__global__ __launch_bounds__(256)
void gemm_xt_kernel(const float* __restrict__ x, const float* __restrict__ tf) {
    extern __shared__ float4 gsm[];
    float4* xs = gsm;              // 64 x 33 float4 (row pad 1)
    float4* ts = gsm + 64*33;
    float*  xn2 = (float*)(gsm + 2*64*33);
    float*  tn2 = xn2 + 64;
    int tid = threadIdx.x;
    int n0 = blockIdx.x*64, m0 = blockIdx.y*64;
    const float4* xg = (const float4*)(x + (size_t)n0*Dd);
    const float4* tg = (const float4*)(tf + (size_t)m0*Dd);
    for (int i = tid; i < 64*32; i += 256) {
        int r = i >> 5, c = i & 31;
        xs[r*33+c] = xg[r*32+c];
        ts[r*33+c] = tg[r*32+c];
    }
    __syncthreads();
    if (tid < 128) {
        int r = tid & 63;
        const float4* src = (tid < 64) ? (xs + r*33) : (ts + r*33);
        float s = 0.0f;
        #pragma unroll 8
        for (int c = 0; c < 32; c++) {
            float4 v = src[c];
            s += v.x*v.x + v.y*v.y + v.z*v.z + v.w*v.w;
        }
        if (tid < 64) xn2[r] = s; else tn2[r] = s;
    }
    __syncthreads();
    int tx = tid & 15, ty = tid >> 4;
    float acc[4][4];
    #pragma unroll
    for (int i = 0; i < 4; i++)
        #pragma unroll
        for (int j = 0; j < 4; j++) acc[i][j] = 0.0f;
    #pragma unroll 4
    for (int k = 0; k < 32; k++) {
        float4 a[4], b[4];
        #pragma unroll
        for (int i = 0; i < 4; i++) a[i] = xs[(ty*4+i)*33 + k];
        #pragma unroll
        for (int j = 0; j < 4; j++) b[j] = ts[(tx*4+j)*33 + k];
        #pragma unroll
        for (int i = 0; i < 4; i++)
            #pragma unroll
            for (int j = 0; j < 4; j++)
                acc[i][j] = fmaf(a[i].x, b[j].x, fmaf(a[i].y, b[j].y,
                             fmaf(a[i].z, b[j].z, fmaf(a[i].w, b[j].w, acc[i][j]))));
    }
    #pragma unroll
    for (int i = 0; i < 4; i++) {
        int n = n0 + ty*4 + i;
        #pragma unroll
        for (int j = 0; j < 4; j++) {
            int m = m0 + tx*4 + j;
            g_XT[(size_t)n*TTe + m] = xn2[ty*4+i] + tn2[tx*4+j] - 2.0f*acc[i][j];
        }
    }
}

// ======================= main kernel =======================
// smem layout (float offsets)
#define NB_O   0     // 17 int
#define RB_O   17    // 17 int (row bitmasks)
#define UB_O   34    // 1 int union mask
#define T1_O   36    // 17 float: alpha*pinv*cnt[k]
#define M_O    64    // 16 * 272
#define KG_O   4416  // 16 * 272   Kt (swizzled) then aliased by G[k*16+m]
#define H_O    8768  // 16 * 272   H[j*16+l]
#define V_O    13120 // 16 * 16
#define SM_FLOATS 13376
#define SM_BYTES (SM_FLOATS*4)

__global__ __launch_bounds__(512, 2)
void ltfgw_kernel(const float* __restrict__ adj,
                  const int*   __restrict__ nbr,
                  const float* __restrict__ tmpl,
                  float* __restrict__ out) {
    extern __shared__ float smf[];
    int*   nb  = (int*)(smf + NB_O);
    int*   rbs = (int*)(smf + RB_O);
    int*   ubp = (int*)(smf + UB_O);
    float* t1f = smf + T1_O;

    const int n    = blockIdx.x;
    const int tid  = threadIdx.x;
    const int lane = tid & 31;
    const int t    = tid >> 5;
    const int l    = lane & 15;
    const int h    = lane >> 4;

    float* Mw  = smf + M_O  + t*272;
    float* KGw = smf + KG_O + t*272;   // Kt (swizzled float4 rows), later G
    float* Hw  = smf + H_O  + t*272;
    float* vsm = smf + V_O  + t*16;

    const float alpha = g_alpha[0];
    const float oneMa = g_alpha[1];
    const float twoA  = 2.0f*alpha;

    // ---- Phase A1: neighbor list ----
    if (tid < K1) nb[tid] = (tid == 0) ? n : nbr[n*Kn + tid - 1];
    __syncthreads();

    // ---- Phase A2: M gather (per warp, LDG from precomputed XT) ----
    #pragma unroll
    for (int ii = 0; ii < 9; ii++) {
        int e = lane + 32*ii;
        if (e < 272) {
            int k = e >> 4;
            Mw[e] = __ldg(&g_XT[(size_t)nb[k]*TTe + t*16 + (e & 15)]);
        }
    }
    // ---- Phase A3 (warp 0): row bitmasks of the binary 17x17 C1 ----
    if (tid < 32) {
        int bits = 0; float cnt = 0.0f;
        if (tid < K1) {
            const float* arow = adj + (size_t)nb[tid]*Nn;
            for (int c = 0; c < K1; c++) {
                float v = arow[nb[c]];
                if (v != 0.0f) { bits |= (1 << c); cnt += 1.0f; }
            }
            rbs[tid] = bits;
            t1f[tid] = alpha * PINV * cnt;   // alpha*cr[k]
        }
        unsigned nz = __ballot_sync(0xffffffffu, bits != 0);
        if (tid == 0) ubp[0] = (int)nz;
    }
    __syncthreads();

    const unsigned UB = (unsigned)ubp[0] & 0x1FFFFu;
    const int lastOuter = (UB == 0u) ? 1 : 3;

    const float qreg  = __ldg(&g_q[t*16 + l]);
    const float ac    = alpha * __ldg(&g_cq2[t*16 + l]);
    const float lanec = 1.0f - 2.0f * __ldg(&g_qc2[t*16 + l]);

    float karr[9];   // K parity layout: karr[ii] = K[2ii+h][l]
    float urow[9];   // urow[ii] = u_{2ii+h}
    float vreg = 1.0f;
    const int swz = (lane >> 1) & 3;   // Kt row-load swizzle for lane==k

    for (int outer = 0; ; outer++) {
        float ge[9];
        // ---------- grad ----------
        if (outer == 0 || UB == 0u) {
            #pragma unroll
            for (int ii = 0; ii < 9; ii++) {
                int e = lane + 32*ii;
                if (e < 272) {
                    int k = e >> 4;
                    ge[ii] = fmaf(oneMa, Mw[e], fmaf(t1f[k], lanec, ac));
                } else ge[ii] = 0.0f;
            }
        } else {
            #pragma unroll
            for (int ii = 0; ii < 9; ii++) {
                int e = lane + 32*ii;
                if (e < 272) {
                    int k = e >> 4;
                    int bits = rbs[k];
                    float s = 0.0f;
                    while (bits) {
                        int j = __ffs(bits) - 1;
                        bits &= bits - 1;
                        s += Hw[j*16 + l];
                    }
                    ge[ii] = fmaf(oneMa, Mw[e], fmaf(-twoA, s, ac + t1f[k]));
                } else ge[ii] = 0.0f;
            }
        }

        if (outer == lastOuter) {
            float acc = 0.0f;
            #pragma unroll
            for (int ii = 0; ii < 9; ii++)
                acc = fmaf(ge[ii], karr[ii]*urow[ii]*vreg, acc);
            #pragma unroll
            for (int s = 16; s > 0; s >>= 1)
                acc += __shfl_xor_sync(0xffffffffu, acc, s);
            if (lane == 0) out[n*Tt + t] = acc;
            break;
        }

        // ---------- eps ----------
        float mn = ge[0], mx = ge[0];
        #pragma unroll
        for (int ii = 1; ii < 8; ii++) { mn = fminf(mn, ge[ii]); mx = fmaxf(mx, ge[ii]); }
        if (lane < 16) { mn = fminf(mn, ge[8]); mx = fmaxf(mx, ge[8]); }
        #pragma unroll
        for (int s = 16; s > 0; s >>= 1) {
            mn = fminf(mn, __shfl_xor_sync(0xffffffffu, mn, s));
            mx = fmaxf(mx, __shfl_xor_sync(0xffffffffu, mx, s));
        }
        float inv_eps = __fdividef(1.0f, 0.1f*(mx - mn) + TINYF);

        // ---------- K = exp; store swizzled Kt ----------
        #pragma unroll
        for (int ii = 0; ii < 9; ii++) {
            int e = lane + 32*ii;
            if (e < 272) {
                float kv = __expf((mn - ge[ii]) * inv_eps);
                karr[ii] = kv;
                int k = 2*ii + h;
                KGw[k*16 + (((l>>2) ^ (ii&3))<<2) + (l&3)] = kv;
            } else karr[ii] = 0.0f;
        }
        __syncwarp();

        // ---------- load my row k=lane into registers (once per outer) ----------
        float4 kr0, kr1, kr2, kr3;
        if (lane < K1) {
            const float4* kt4 = (const float4*)KGw;
            kr0 = kt4[lane*4 + (0^swz)];
            kr1 = kt4[lane*4 + (1^swz)];
            kr2 = kt4[lane*4 + (2^swz)];
            kr3 = kt4[lane*4 + (3^swz)];
        }
        __syncwarp();   // Kt region free for G after this

        // ---------- Sinkhorn ----------
        // u-step 1 (v = 1): row sum
        float u;
        {
            float S = 1.0f;
            if (lane < K1) {
                S = kr0.x + kr0.y + kr0.z + kr0.w
                  + kr1.x + kr1.y + kr1.z + kr1.w
                  + kr2.x + kr2.y + kr2.z + kr2.w
                  + kr3.x + kr3.y + kr3.z + kr3.w;
            }
            u = __fdividef(PINV, fmaxf(S, TINYF));
        }
        #pragma unroll
        for (int it = 0; it < 5; it++) {
            // gather u into parity layout
            #pragma unroll
            for (int ii = 0; ii < 9; ii++)
                urow[ii] = __shfl_sync(0xffffffffu, u, 2*ii + h);
            // v-step (register column sums)
            float sv = 0.0f;
            #pragma unroll
            for (int r = 0; r < 9; r++) sv = fmaf(karr[r], urow[r], sv);
            sv += __shfl_xor_sync(0xffffffffu, sv, 16);
            vreg = __fdividef(qreg, fmaxf(sv, TINYF));
            if (it == 4) break;
            // publish v, then register-local u-step
            if (lane < 16) vsm[lane] = vreg;
            __syncwarp();
            {
                float S = 1.0f;
                if (lane < K1) {
                    const float4* vv4 = (const float4*)vsm;
                    float4 v0 = vv4[0], v1 = vv4[1], v2 = vv4[2], v3 = vv4[3];
                    S =          kr0.x*v0.x;
                    S = fmaf(kr0.y, v0.y, S); S = fmaf(kr0.z, v0.z, S); S = fmaf(kr0.w, v0.w, S);
                    S = fmaf(kr1.x, v1.x, S); S = fmaf(kr1.y, v1.y, S); S = fmaf(kr1.z, v1.z, S); S = fmaf(kr1.w, v1.w, S);
                    S = fmaf(kr2.x, v2.x, S); S = fmaf(kr2.y, v2.y, S); S = fmaf(kr2.z, v2.z, S); S = fmaf(kr2.w, v2.w, S);
                    S = fmaf(kr3.x, v3.x, S); S = fmaf(kr3.y, v3.y, S); S = fmaf(kr3.z, v3.z, S); S = fmaf(kr3.w, v3.w, S);
                }
                u = __fdividef(PINV, fmaxf(S, TINYF));
            }
        }

        // ---------- G to smem (aliases Kt) + H build (only if C1 nonzero) ----------
        if (UB) {
            #pragma unroll
            for (int ii = 0; ii < 9; ii++) {
                int e = lane + 32*ii;
                if (e < 272) KGw[e] = karr[ii]*urow[ii]*vreg;  // conflict-free
            }
            __syncwarp();
            // C2 row l via texture path (L1-resident)
            const float4* tp = (const float4*)(tmpl + (t*16 + l)*16);
            float4 c0 = __ldg(tp+0), c1 = __ldg(tp+1), c2 = __ldg(tp+2), c3 = __ldg(tp+3);
            #pragma unroll
            for (int j = 0; j < 17; j++) {
                if ((UB >> j) & 1u) {
                    const float4* gr = (const float4*)(KGw + j*16);
                    float4 a = gr[0], b = gr[1], c = gr[2], d = gr[3];
                    float s =            a.x*c0.x;
                    s = fmaf(a.y, c0.y, s); s = fmaf(a.z, c0.z, s); s = fmaf(a.w, c0.w, s);
                    s = fmaf(b.x, c1.x, s); s = fmaf(b.y, c1.y, s); s = fmaf(b.z, c1.z, s); s = fmaf(b.w, c1.w, s);
                    s = fmaf(c.x, c2.x, s); s = fmaf(c.y, c2.y, s); s = fmaf(c.z, c2.z, s); s = fmaf(c.w, c2.w, s);
                    s = fmaf(d.x, c3.x, s); s = fmaf(d.y, c3.y, s); s = fmaf(d.z, c3.z, s); s = fmaf(d.w, c3.w, s);
                    if (lane < 16) Hw[j*16 + l] = s;
                }
            }
            __syncwarp();
        }
    }
}

extern "C" void kernel_launch(void* const* d_in, const int* in_sizes, int n_in,
                              void* d_out, int out_size) {
    const float* x    = (const float*)d_in[0];
    const float* adj  = (const float*)d_in[1];
    const int*   nbr  = (const int*)  d_in[2];
    const float* tmpl = (const float*)d_in[3];
    const float* tf   = (const float*)d_in[4];
    const float* q0   = (const float*)d_in[5];
    const float* a0   = (const float*)d_in[6];
    float* out = (float*)d_out;

    cudaFuncSetAttribute(gemm_xt_kernel, cudaFuncAttributeMaxDynamicSharedMemorySize, GSM_BYTES);
    cudaFuncSetAttribute(ltfgw_kernel,   cudaFuncAttributeMaxDynamicSharedMemorySize, SM_BYTES);

    setup_kernel<<<1, 256>>>(q0, tmpl, a0);
    dim3 ggrid(Nn/64, TTe/64);
    gemm_xt_kernel<<<ggrid, 256, GSM_BYTES>>>(x, tf);
    ltfgw_kernel<<<Nn, 512, SM_BYTES>>>(adj, nbr, tmpl, out);
    (void)in_sizes; (void)n_in; (void)out_size;
}